// round 3
// baseline (speedup 1.0000x reference)
#include <cuda_runtime.h>
#include <math.h>

#define C   64
#define HW  64
#define NSP 4096          // N = HW*HW spatial positions
#define BB  8             // batch
#define EPSBN 1e-5f

// attention tiling
#define TNQ 128           // query rows per CTA
#define TMK 64            // key/value chunk
#define PQ  136           // Q smem pitch (d-major [64][128])
#define PK  72            // K smem pitch (d-major [64][64])
#define PVP 68            // V smem pitch (d-major [64][64])
#define SMEM_U32 (64*PQ + 64*PK + 64*PVP)   // 17664 u32 = 70656 B

// scratch (no allocations allowed -> device globals)
__device__ float g_V[BB * C * NSP];     // after conv1+bn1+relu
__device__ float g_attn[BB * C * NSP];  // attention output
__device__ float g_U[BB * C * NSP];     // after depthwise+bn2+relu

// ---------------------------------------------------------------------------
// helpers
// ---------------------------------------------------------------------------
__device__ __forceinline__ unsigned f2tf32(float f) {
    unsigned u;
    asm("cvt.rna.tf32.f32 %0, %1;" : "=r"(u) : "f"(f));
    return u;
}

__device__ __forceinline__ void mma_tf32(float c[4],
                                         unsigned a0, unsigned a1, unsigned a2, unsigned a3,
                                         unsigned b0, unsigned b1) {
    asm volatile(
        "mma.sync.aligned.m16n8k8.row.col.f32.tf32.tf32.f32 "
        "{%0,%1,%2,%3},{%4,%5,%6,%7},{%8,%9},{%0,%1,%2,%3};\n"
        : "+f"(c[0]), "+f"(c[1]), "+f"(c[2]), "+f"(c[3])
        : "r"(a0), "r"(a1), "r"(a2), "r"(a3), "r"(b0), "r"(b1));
}

// ---------------------------------------------------------------------------
// conv1x1 (w1) + BN1 + ReLU  ->  g_V
// 256 threads: 128 positions x 2 output halves
// ---------------------------------------------------------------------------
__global__ __launch_bounds__(256) void conv1_kernel(
    const float* __restrict__ x, const float* __restrict__ w1,
    const float* __restrict__ g, const float* __restrict__ bb,
    const float* __restrict__ m, const float* __restrict__ v)
{
    __shared__ float ws[C * C];
    __shared__ float s_inv[C], s_shift[C];
    int tid = threadIdx.x;
    for (int i = tid; i < C * C; i += 256) ws[i] = w1[i];
    if (tid < C) {
        float inv = g[tid] * rsqrtf(v[tid] + EPSBN);
        s_inv[tid] = inv;
        s_shift[tid] = bb[tid] - m[tid] * inv;
    }
    __syncthreads();

    int h = tid >> 7;                 // output half (warp-uniform)
    int p = tid & 127;
    int b = blockIdx.y;
    int n = blockIdx.x * 128 + p;
    const float* xp = x + (size_t)b * C * NSP + n;
    float xv[C];
#pragma unroll
    for (int c = 0; c < C; c++) xv[c] = xp[(size_t)c * NSP];

    float* op = g_V + (size_t)b * C * NSP + n;
    int o0 = h * 32;
#pragma unroll 4
    for (int o = o0; o < o0 + 32; o++) {
        const float4* wr = (const float4*)(ws + o * C);
        float a0 = 0.f, a1 = 0.f, a2 = 0.f, a3 = 0.f;
#pragma unroll
        for (int k = 0; k < 16; k++) {
            float4 f = wr[k];
            a0 += f.x * xv[4 * k + 0];
            a1 += f.y * xv[4 * k + 1];
            a2 += f.z * xv[4 * k + 2];
            a3 += f.w * xv[4 * k + 3];
        }
        float acc = (a0 + a1) + (a2 + a3);
        float r = acc * s_inv[o] + s_shift[o];
        op[(size_t)o * NSP] = fmaxf(r, 0.f);
    }
}

// ---------------------------------------------------------------------------
// flash attention, tf32 mma.sync. CTA = (batch, 128 rows); 4 warps x 32 rows.
// K/V B-fragments loaded once per warp, reused across both 16-row blocks.
// ---------------------------------------------------------------------------
__global__ __launch_bounds__(128, 2) void attn_mma_kernel(const float* __restrict__ x)
{
    extern __shared__ unsigned smem_u[];
    unsigned* Qu = smem_u;            // [d][i]  64 x 128, pitch PQ
    unsigned* Ku = Qu + 64 * PQ;      // [d][j]  64 x 64,  pitch PK
    unsigned* Vu = Ku + 64 * PK;      // [d][j]  64 x 64,  pitch PVP

    const int tid  = threadIdx.x;
    const int lane = tid & 31;
    const int wid  = tid >> 5;        // 0..3
    const int g    = lane >> 2;       // 0..7
    const int q    = lane & 3;        // 0..3
    const int i0   = wid * 32;        // warp's 32-row base

    const int b  = blockIdx.y;
    const int n0 = blockIdx.x * TNQ;
    const float* xb = x   + (size_t)b * C * NSP;
    const float* vb = g_V + (size_t)b * C * NSP;

    // load Q tile (scale 1/8 folded in)
    for (int idx = tid; idx < 64 * TNQ; idx += 128) {
        int d = idx >> 7, i = idx & 127;
        Qu[d * PQ + i] = f2tf32(xb[(size_t)d * NSP + n0 + i] * 0.125f);
    }

    float SC[2][8][4];                // S/P fragments, 2 row-blocks x 64 cols
    float OC[2][8][4];                // O accumulators
#pragma unroll
    for (int rb = 0; rb < 2; rb++)
#pragma unroll
        for (int t = 0; t < 8; t++)
            OC[rb][t][0] = OC[rb][t][1] = OC[rb][t][2] = OC[rb][t][3] = 0.f;
    float rm[2][2], rl[2][2];
#pragma unroll
    for (int rb = 0; rb < 2; rb++) {
        rm[rb][0] = rm[rb][1] = -1e30f;
        rl[rb][0] = rl[rb][1] = 0.f;
    }

    const int base = lane & ~3;
    const int srcA = base | (q >> 1);
    const int srcB = srcA + 2;
    const bool odd = lane & 1;

    for (int m0 = 0; m0 < NSP; m0 += TMK) {
        __syncthreads();              // prev PV done reading K/V
        // ---- load K/V chunk (coalesced d-major) ----
        for (int idx = tid; idx < 64 * TMK; idx += 128) {
            int d = idx >> 6, j = idx & 63;
            Ku[d * PK  + j] = f2tf32(xb[(size_t)d * NSP + m0 + j]);
            Vu[d * PVP + j] = f2tf32(vb[(size_t)d * NSP + m0 + j]);
        }
        __syncthreads();

        // ---- S = Q K^T (B loads shared across row-blocks) ----
#pragma unroll
        for (int rb = 0; rb < 2; rb++)
#pragma unroll
            for (int t = 0; t < 8; t++)
                SC[rb][t][0] = SC[rb][t][1] = SC[rb][t][2] = SC[rb][t][3] = 0.f;
#pragma unroll
        for (int kt = 0; kt < 8; kt++) {
            int r = kt * 8 + q;
            unsigned aA0 = Qu[r * PQ + i0 + g];
            unsigned aA1 = Qu[r * PQ + i0 + g + 8];
            unsigned aA2 = Qu[(r + 4) * PQ + i0 + g];
            unsigned aA3 = Qu[(r + 4) * PQ + i0 + g + 8];
            unsigned aB0 = Qu[r * PQ + i0 + 16 + g];
            unsigned aB1 = Qu[r * PQ + i0 + 16 + g + 8];
            unsigned aB2 = Qu[(r + 4) * PQ + i0 + 16 + g];
            unsigned aB3 = Qu[(r + 4) * PQ + i0 + 16 + g + 8];
#pragma unroll
            for (int nt = 0; nt < 8; nt++) {
                unsigned b0 = Ku[r * PK + nt * 8 + g];
                unsigned b1 = Ku[(r + 4) * PK + nt * 8 + g];
                mma_tf32(SC[0][nt], aA0, aA1, aA2, aA3, b0, b1);
                mma_tf32(SC[1][nt], aB0, aB1, aB2, aB3, b0, b1);
            }
        }

        // ---- online softmax per row-block ----
        float cs[2][2];
#pragma unroll
        for (int rb = 0; rb < 2; rb++) {
            float mx0 = -1e30f, mx1 = -1e30f;
#pragma unroll
            for (int nt = 0; nt < 8; nt++) {
                mx0 = fmaxf(mx0, fmaxf(SC[rb][nt][0], SC[rb][nt][1]));
                mx1 = fmaxf(mx1, fmaxf(SC[rb][nt][2], SC[rb][nt][3]));
            }
            mx0 = fmaxf(mx0, __shfl_xor_sync(0xffffffffu, mx0, 1));
            mx0 = fmaxf(mx0, __shfl_xor_sync(0xffffffffu, mx0, 2));
            mx1 = fmaxf(mx1, __shfl_xor_sync(0xffffffffu, mx1, 1));
            mx1 = fmaxf(mx1, __shfl_xor_sync(0xffffffffu, mx1, 2));

            float mn0 = fmaxf(rm[rb][0], mx0), mn1 = fmaxf(rm[rb][1], mx1);
            float c0 = __expf(rm[rb][0] - mn0), c1 = __expf(rm[rb][1] - mn1);
            rm[rb][0] = mn0; rm[rb][1] = mn1;

            float ls0 = 0.f, ls1 = 0.f;
#pragma unroll
            for (int nt = 0; nt < 8; nt++) {
                SC[rb][nt][0] = __expf(SC[rb][nt][0] - mn0); ls0 += SC[rb][nt][0];
                SC[rb][nt][1] = __expf(SC[rb][nt][1] - mn0); ls0 += SC[rb][nt][1];
                SC[rb][nt][2] = __expf(SC[rb][nt][2] - mn1); ls1 += SC[rb][nt][2];
                SC[rb][nt][3] = __expf(SC[rb][nt][3] - mn1); ls1 += SC[rb][nt][3];
            }
            ls0 += __shfl_xor_sync(0xffffffffu, ls0, 1);
            ls0 += __shfl_xor_sync(0xffffffffu, ls0, 2);
            ls1 += __shfl_xor_sync(0xffffffffu, ls1, 1);
            ls1 += __shfl_xor_sync(0xffffffffu, ls1, 2);
            rl[rb][0] = rl[rb][0] * c0 + ls0;
            rl[rb][1] = rl[rb][1] * c1 + ls1;
            cs[rb][0] = c0; cs[rb][1] = c1;

            // rescale O, convert P to tf32 bits
#pragma unroll
            for (int t = 0; t < 8; t++) {
                OC[rb][t][0] *= c0; OC[rb][t][1] *= c0;
                OC[rb][t][2] *= c1; OC[rb][t][3] *= c1;
                SC[rb][t][0] = __uint_as_float(f2tf32(SC[rb][t][0]));
                SC[rb][t][1] = __uint_as_float(f2tf32(SC[rb][t][1]));
                SC[rb][t][2] = __uint_as_float(f2tf32(SC[rb][t][2]));
                SC[rb][t][3] = __uint_as_float(f2tf32(SC[rb][t][3]));
            }
        }

        // ---- O += P V : V B-fragments shared across row-blocks ----
#pragma unroll
        for (int jt = 0; jt < 8; jt++) {
            unsigned aA0, aA1, aA2, aA3, aB0, aB1, aB2, aB3;
            {
                float p0 = SC[0][jt][0], p1 = SC[0][jt][1], p2 = SC[0][jt][2], p3 = SC[0][jt][3];
                float q0A = __shfl_sync(0xffffffffu, p0, srcA);
                float q1A = __shfl_sync(0xffffffffu, p1, srcA);
                float q2A = __shfl_sync(0xffffffffu, p2, srcA);
                float q3A = __shfl_sync(0xffffffffu, p3, srcA);
                float q0B = __shfl_sync(0xffffffffu, p0, srcB);
                float q1B = __shfl_sync(0xffffffffu, p1, srcB);
                float q2B = __shfl_sync(0xffffffffu, p2, srcB);
                float q3B = __shfl_sync(0xffffffffu, p3, srcB);
                aA0 = __float_as_uint(odd ? q1A : q0A);
                aA1 = __float_as_uint(odd ? q3A : q2A);
                aA2 = __float_as_uint(odd ? q1B : q0B);
                aA3 = __float_as_uint(odd ? q3B : q2B);
            }
            {
                float p0 = SC[1][jt][0], p1 = SC[1][jt][1], p2 = SC[1][jt][2], p3 = SC[1][jt][3];
                float q0A = __shfl_sync(0xffffffffu, p0, srcA);
                float q1A = __shfl_sync(0xffffffffu, p1, srcA);
                float q2A = __shfl_sync(0xffffffffu, p2, srcA);
                float q3A = __shfl_sync(0xffffffffu, p3, srcA);
                float q0B = __shfl_sync(0xffffffffu, p0, srcB);
                float q1B = __shfl_sync(0xffffffffu, p1, srcB);
                float q2B = __shfl_sync(0xffffffffu, p2, srcB);
                float q3B = __shfl_sync(0xffffffffu, p3, srcB);
                aB0 = __float_as_uint(odd ? q1A : q0A);
                aB1 = __float_as_uint(odd ? q3A : q2A);
                aB2 = __float_as_uint(odd ? q1B : q0B);
                aB3 = __float_as_uint(odd ? q3B : q2B);
            }
#pragma unroll
            for (int nt2 = 0; nt2 < 8; nt2++) {
                unsigned b0 = Vu[(nt2 * 8 + g) * PVP + jt * 8 + q];
                unsigned b1 = Vu[(nt2 * 8 + g) * PVP + jt * 8 + q + 4];
                mma_tf32(OC[0][nt2], aA0, aA1, aA2, aA3, b0, b1);
                mma_tf32(OC[1][nt2], aB0, aB1, aB2, aB3, b0, b1);
            }
        }
    }

    // ---- normalize + write ----
#pragma unroll
    for (int rb = 0; rb < 2; rb++) {
        float inv0 = 1.f / rl[rb][0], inv1 = 1.f / rl[rb][1];
        float* ob = g_attn + (size_t)b * C * NSP + n0 + i0 + rb * 16 + g;
#pragma unroll
        for (int nt2 = 0; nt2 < 8; nt2++) {
            int d0 = nt2 * 8 + 2 * q;
            ob[(size_t)d0 * NSP]           = OC[rb][nt2][0] * inv0;
            ob[(size_t)(d0 + 1) * NSP]     = OC[rb][nt2][1] * inv0;
            ob[(size_t)d0 * NSP + 8]       = OC[rb][nt2][2] * inv1;
            ob[(size_t)(d0 + 1) * NSP + 8] = OC[rb][nt2][3] * inv1;
        }
    }
}

// ---------------------------------------------------------------------------
// depthwise 3x3 SAME (w2) + BN2 + ReLU : g_attn -> g_U
// ---------------------------------------------------------------------------
__global__ __launch_bounds__(256) void dw_kernel(
    const float* __restrict__ w2,
    const float* __restrict__ g, const float* __restrict__ bb,
    const float* __restrict__ m, const float* __restrict__ v)
{
    int idx = blockIdx.x * 256 + threadIdx.x;      // over BB*C*NSP
    int xw = idx & (HW - 1);
    int rest = idx >> 6;
    int y = rest & (HW - 1);
    rest >>= 6;
    int c = rest & (C - 1);
    const float* ip = g_attn + ((size_t)(idx >> 12) << 12);  // (b,c) plane base
    float acc = 0.f;
#pragma unroll
    for (int dy = -1; dy <= 1; dy++) {
        int yy = y + dy;
        if (yy < 0 || yy >= HW) continue;
#pragma unroll
        for (int dx = -1; dx <= 1; dx++) {
            int xx = xw + dx;
            if (xx < 0 || xx >= HW) continue;
            acc += ip[yy * HW + xx] * w2[c * 9 + (dy + 1) * 3 + (dx + 1)];
        }
    }
    float inv = g[c] * rsqrtf(v[c] + EPSBN);
    float r = acc * inv + (bb[c] - m[c] * inv);
    g_U[idx] = fmaxf(r, 0.f);
}

// ---------------------------------------------------------------------------
// conv1x1 (w3) + BN3 + residual(x) -> out
// ---------------------------------------------------------------------------
__global__ __launch_bounds__(256) void conv3_kernel(
    const float* __restrict__ w3,
    const float* __restrict__ g, const float* __restrict__ bb,
    const float* __restrict__ m, const float* __restrict__ v,
    const float* __restrict__ x, float* __restrict__ out)
{
    __shared__ float ws[C * C];
    __shared__ float s_inv[C], s_shift[C];
    int tid = threadIdx.x;
    for (int i = tid; i < C * C; i += 256) ws[i] = w3[i];
    if (tid < C) {
        float inv = g[tid] * rsqrtf(v[tid] + EPSBN);
        s_inv[tid] = inv;
        s_shift[tid] = bb[tid] - m[tid] * inv;
    }
    __syncthreads();

    int h = tid >> 7;
    int p = tid & 127;
    int b = blockIdx.y;
    int n = blockIdx.x * 128 + p;
    const float* up = g_U + (size_t)b * C * NSP + n;
    float uv[C];
#pragma unroll
    for (int c = 0; c < C; c++) uv[c] = up[(size_t)c * NSP];

    const float* xp = x + (size_t)b * C * NSP + n;
    float* op = out + (size_t)b * C * NSP + n;
    int o0 = h * 32;
#pragma unroll 4
    for (int o = o0; o < o0 + 32; o++) {
        const float4* wr = (const float4*)(ws + o * C);
        float a0 = 0.f, a1 = 0.f, a2 = 0.f, a3 = 0.f;
#pragma unroll
        for (int k = 0; k < 16; k++) {
            float4 f = wr[k];
            a0 += f.x * uv[4 * k + 0];
            a1 += f.y * uv[4 * k + 1];
            a2 += f.z * uv[4 * k + 2];
            a3 += f.w * uv[4 * k + 3];
        }
        float acc = (a0 + a1) + (a2 + a3);
        float r = acc * s_inv[o] + s_shift[o] + xp[(size_t)o * NSP];
        op[(size_t)o * NSP] = r;
    }
}

// ---------------------------------------------------------------------------
extern "C" void kernel_launch(void* const* d_in, const int* in_sizes, int n_in,
                              void* d_out, int out_size)
{
    const float* x    = (const float*)d_in[0];
    const float* w1   = (const float*)d_in[1];
    const float* bn1g = (const float*)d_in[2];
    const float* bn1b = (const float*)d_in[3];
    const float* bn1m = (const float*)d_in[4];
    const float* bn1v = (const float*)d_in[5];
    const float* w2   = (const float*)d_in[6];
    const float* bn2g = (const float*)d_in[7];
    const float* bn2b = (const float*)d_in[8];
    const float* bn2m = (const float*)d_in[9];
    const float* bn2v = (const float*)d_in[10];
    const float* w3   = (const float*)d_in[11];
    const float* bn3g = (const float*)d_in[12];
    const float* bn3b = (const float*)d_in[13];
    const float* bn3m = (const float*)d_in[14];
    const float* bn3v = (const float*)d_in[15];
    float* out = (float*)d_out;

    static int smem_set = 0;
    if (!smem_set) {
        cudaFuncSetAttribute(attn_mma_kernel,
                             cudaFuncAttributeMaxDynamicSharedMemorySize,
                             SMEM_U32 * 4);
        smem_set = 1;
    }

    conv1_kernel<<<dim3(NSP / 128, BB), 256>>>(x, w1, bn1g, bn1b, bn1m, bn1v);
    attn_mma_kernel<<<dim3(NSP / TNQ, BB), 128, SMEM_U32 * 4>>>(x);
    dw_kernel<<<(BB * C * NSP) / 256, 256>>>(w2, bn2g, bn2b, bn2m, bn2v);
    conv3_kernel<<<dim3(NSP / 128, BB), 256>>>(w3, bn3g, bn3b, bn3m, bn3v, x, out);
}

// round 4
// speedup vs baseline: 1.1860x; 1.1860x over previous
#include <cuda_runtime.h>
#include <math.h>

#define C   64
#define HW  64
#define NSP 4096          // N = HW*HW spatial positions
#define BB  8             // batch
#define EPSBN 1e-5f

// attention tiling
#define TNQ 128           // query rows per CTA
#define TMK 64            // key/value chunk
#define PQ  136           // Q smem pitch (d-major [64][128])
#define PK  72            // K smem pitch (d-major [64][64])
#define PVP 68            // V smem pitch (d-major [64][64])
#define SMEM_U32 (64*PQ + 64*PK + 64*PVP)   // 17664 u32 = 70656 B

// scale: (1/8) * log2(e)  -> logits land in log2 domain, exp == exp2
#define QSCALE 0.18033688f

// scratch (no allocations allowed -> device globals)
__device__ float g_V[BB * C * NSP];     // after conv1+bn1+relu
__device__ float g_attn[BB * C * NSP];  // attention output
__device__ float g_U[BB * C * NSP];     // after depthwise+bn2+relu

// ---------------------------------------------------------------------------
// helpers
// ---------------------------------------------------------------------------
__device__ __forceinline__ unsigned f2tf32(float f) {
    unsigned u;
    asm("cvt.rna.tf32.f32 %0, %1;" : "=r"(u) : "f"(f));
    return u;
}

__device__ __forceinline__ void mma_tf32(float c[4],
                                         unsigned a0, unsigned a1, unsigned a2, unsigned a3,
                                         unsigned b0, unsigned b1) {
    asm volatile(
        "mma.sync.aligned.m16n8k8.row.col.f32.tf32.tf32.f32 "
        "{%0,%1,%2,%3},{%4,%5,%6,%7},{%8,%9},{%0,%1,%2,%3};\n"
        : "+f"(c[0]), "+f"(c[1]), "+f"(c[2]), "+f"(c[3])
        : "r"(a0), "r"(a1), "r"(a2), "r"(a3), "r"(b0), "r"(b1));
}

// ---------------------------------------------------------------------------
// conv1x1 (w1) + BN1 + ReLU  ->  g_V
// ---------------------------------------------------------------------------
__global__ __launch_bounds__(256) void conv1_kernel(
    const float* __restrict__ x, const float* __restrict__ w1,
    const float* __restrict__ g, const float* __restrict__ bb,
    const float* __restrict__ m, const float* __restrict__ v)
{
    __shared__ float ws[C * C];
    __shared__ float s_inv[C], s_shift[C];
    int tid = threadIdx.x;
    for (int i = tid; i < C * C; i += 256) ws[i] = w1[i];
    if (tid < C) {
        float inv = g[tid] * rsqrtf(v[tid] + EPSBN);
        s_inv[tid] = inv;
        s_shift[tid] = bb[tid] - m[tid] * inv;
    }
    __syncthreads();

    int h = tid >> 7;                 // output half (warp-uniform)
    int p = tid & 127;
    int b = blockIdx.y;
    int n = blockIdx.x * 128 + p;
    const float* xp = x + (size_t)b * C * NSP + n;
    float xv[C];
#pragma unroll
    for (int c = 0; c < C; c++) xv[c] = xp[(size_t)c * NSP];

    float* op = g_V + (size_t)b * C * NSP + n;
    int o0 = h * 32;
#pragma unroll 4
    for (int o = o0; o < o0 + 32; o++) {
        const float4* wr = (const float4*)(ws + o * C);
        float a0 = 0.f, a1 = 0.f, a2 = 0.f, a3 = 0.f;
#pragma unroll
        for (int k = 0; k < 16; k++) {
            float4 f = wr[k];
            a0 += f.x * xv[4 * k + 0];
            a1 += f.y * xv[4 * k + 1];
            a2 += f.z * xv[4 * k + 2];
            a3 += f.w * xv[4 * k + 3];
        }
        float acc = (a0 + a1) + (a2 + a3);
        float r = acc * s_inv[o] + s_shift[o];
        op[(size_t)o * NSP] = fmaxf(r, 0.f);
    }
}

// ---------------------------------------------------------------------------
// flash attention, tf32 mma.sync, NO-MAX softmax (logits bounded ~15 << 88).
// CTA = (batch, 128 query rows); 8 warps; warp owns 16 rows x all 64 cols.
// ---------------------------------------------------------------------------
__global__ __launch_bounds__(256, 2) void attn_mma_kernel(const float* __restrict__ x)
{
    extern __shared__ unsigned smem_u[];
    unsigned* Qu = smem_u;            // [d][i]  64 x 128, pitch PQ
    unsigned* Ku = Qu + 64 * PQ;      // [d][j]  64 x 64,  pitch PK
    unsigned* Vu = Ku + 64 * PK;      // [d][j]  64 x 64,  pitch PVP

    const int tid  = threadIdx.x;
    const int lane = tid & 31;
    const int wid  = tid >> 5;
    const int g    = lane >> 2;       // group id 0..7
    const int q    = lane & 3;        // 0..3
    const int i0   = wid * 16;        // warp's row base within CTA tile

    const int b  = blockIdx.y;
    const int n0 = blockIdx.x * TNQ;
    const float* xb = x   + (size_t)b * C * NSP;
    const float* vb = g_V + (size_t)b * C * NSP;

    // load Q tile (scale (1/8)*log2e folded in)
    for (int idx = tid; idx < 64 * TNQ; idx += 256) {
        int d = idx >> 7, i = idx & 127;
        Qu[d * PQ + i] = f2tf32(xb[(size_t)d * NSP + n0 + i] * QSCALE);
    }

    float SC[8][4];                   // S / P fragments (warp's 16 x 64 tile)
    float OC[8][4];                   // O accumulators   (16 rows x 64 dims)
#pragma unroll
    for (int t = 0; t < 8; t++) { OC[t][0] = OC[t][1] = OC[t][2] = OC[t][3] = 0.f; }
    float rl0 = 0.f, rl1 = 0.f;       // per-lane partial row sums (rows g, g+8)

    const int base = lane & ~3;
    const int srcA = base | (q >> 1);
    const int srcB = srcA + 2;
    const bool odd = lane & 1;

    __syncthreads();

    for (int m0 = 0; m0 < NSP; m0 += TMK) {
        // ---- load K/V chunk (coalesced d-major) ----
        {
            for (int idx = tid; idx < 64 * TMK; idx += 256) {
                int d = idx >> 6, j = idx & 63;
                Ku[d * PK  + j] = f2tf32(xb[(size_t)d * NSP + m0 + j]);
                Vu[d * PVP + j] = f2tf32(vb[(size_t)d * NSP + m0 + j]);
            }
        }
        __syncthreads();

        // ---- S = Q K^T (log2-domain, scaled) ----
#pragma unroll
        for (int t = 0; t < 8; t++) { SC[t][0] = SC[t][1] = SC[t][2] = SC[t][3] = 0.f; }
#pragma unroll
        for (int kt = 0; kt < 8; kt++) {
            int r = kt * 8 + q;
            unsigned a0 = Qu[r * PQ + i0 + g];
            unsigned a1 = Qu[r * PQ + i0 + g + 8];
            unsigned a2 = Qu[(r + 4) * PQ + i0 + g];
            unsigned a3 = Qu[(r + 4) * PQ + i0 + g + 8];
#pragma unroll
            for (int nt = 0; nt < 8; nt++) {
                unsigned b0 = Ku[r * PK + nt * 8 + g];
                unsigned b1 = Ku[(r + 4) * PK + nt * 8 + g];
                mma_tf32(SC[nt], a0, a1, a2, a3, b0, b1);
            }
        }

        // ---- P = exp2(S); accumulate per-lane row sums; cvt to tf32 ----
#pragma unroll
        for (int nt = 0; nt < 8; nt++) {
            float e0 = exp2f(SC[nt][0]);
            float e1 = exp2f(SC[nt][1]);
            float e2 = exp2f(SC[nt][2]);
            float e3 = exp2f(SC[nt][3]);
            rl0 += e0 + e1;
            rl1 += e2 + e3;
            SC[nt][0] = __uint_as_float(f2tf32(e0));
            SC[nt][1] = __uint_as_float(f2tf32(e1));
            SC[nt][2] = __uint_as_float(f2tf32(e2));
            SC[nt][3] = __uint_as_float(f2tf32(e3));
        }

        // ---- O += P V : A fragments built from SC via lane permute ----
#pragma unroll
        for (int jt = 0; jt < 8; jt++) {
            float p0 = SC[jt][0], p1 = SC[jt][1], p2 = SC[jt][2], p3 = SC[jt][3];
            float q0A = __shfl_sync(0xffffffffu, p0, srcA);
            float q1A = __shfl_sync(0xffffffffu, p1, srcA);
            float q2A = __shfl_sync(0xffffffffu, p2, srcA);
            float q3A = __shfl_sync(0xffffffffu, p3, srcA);
            float q0B = __shfl_sync(0xffffffffu, p0, srcB);
            float q1B = __shfl_sync(0xffffffffu, p1, srcB);
            float q2B = __shfl_sync(0xffffffffu, p2, srcB);
            float q3B = __shfl_sync(0xffffffffu, p3, srcB);
            unsigned a0 = __float_as_uint(odd ? q1A : q0A);   // row g,   col jt*8+q
            unsigned a1 = __float_as_uint(odd ? q3A : q2A);   // row g+8, col jt*8+q
            unsigned a2 = __float_as_uint(odd ? q1B : q0B);   // row g,   col jt*8+q+4
            unsigned a3 = __float_as_uint(odd ? q3B : q2B);   // row g+8, col jt*8+q+4
#pragma unroll
            for (int nt2 = 0; nt2 < 8; nt2++) {
                unsigned b0 = Vu[(nt2 * 8 + g) * PVP + jt * 8 + q];
                unsigned b1 = Vu[(nt2 * 8 + g) * PVP + jt * 8 + q + 4];
                mma_tf32(OC[nt2], a0, a1, a2, a3, b0, b1);
            }
        }
        __syncthreads();
    }

    // ---- final row-sum reduction (once, not per chunk) ----
    rl0 += __shfl_xor_sync(0xffffffffu, rl0, 1);
    rl0 += __shfl_xor_sync(0xffffffffu, rl0, 2);
    rl1 += __shfl_xor_sync(0xffffffffu, rl1, 1);
    rl1 += __shfl_xor_sync(0xffffffffu, rl1, 2);

    // ---- normalize + write ----
    {
        float inv0 = 1.f / rl0, inv1 = 1.f / rl1;
        float* ob = g_attn + (size_t)b * C * NSP + n0 + i0 + g;
#pragma unroll
        for (int nt2 = 0; nt2 < 8; nt2++) {
            int d0 = nt2 * 8 + 2 * q;
            ob[(size_t)d0 * NSP]           = OC[nt2][0] * inv0;
            ob[(size_t)(d0 + 1) * NSP]     = OC[nt2][1] * inv0;
            ob[(size_t)d0 * NSP + 8]       = OC[nt2][2] * inv1;
            ob[(size_t)(d0 + 1) * NSP + 8] = OC[nt2][3] * inv1;
        }
    }
}

// ---------------------------------------------------------------------------
// depthwise 3x3 SAME (w2) + BN2 + ReLU : g_attn -> g_U
// ---------------------------------------------------------------------------
__global__ __launch_bounds__(256) void dw_kernel(
    const float* __restrict__ w2,
    const float* __restrict__ g, const float* __restrict__ bb,
    const float* __restrict__ m, const float* __restrict__ v)
{
    int idx = blockIdx.x * 256 + threadIdx.x;      // over BB*C*NSP
    int xw = idx & (HW - 1);
    int rest = idx >> 6;
    int y = rest & (HW - 1);
    rest >>= 6;
    int c = rest & (C - 1);
    const float* ip = g_attn + ((size_t)(idx >> 12) << 12);  // (b,c) plane base
    float acc = 0.f;
#pragma unroll
    for (int dy = -1; dy <= 1; dy++) {
        int yy = y + dy;
        if (yy < 0 || yy >= HW) continue;
#pragma unroll
        for (int dx = -1; dx <= 1; dx++) {
            int xx = xw + dx;
            if (xx < 0 || xx >= HW) continue;
            acc += ip[yy * HW + xx] * w2[c * 9 + (dy + 1) * 3 + (dx + 1)];
        }
    }
    float inv = g[c] * rsqrtf(v[c] + EPSBN);
    float r = acc * inv + (bb[c] - m[c] * inv);
    g_U[idx] = fmaxf(r, 0.f);
}

// ---------------------------------------------------------------------------
// conv1x1 (w3) + BN3 + residual(x) -> out
// ---------------------------------------------------------------------------
__global__ __launch_bounds__(256) void conv3_kernel(
    const float* __restrict__ w3,
    const float* __restrict__ g, const float* __restrict__ bb,
    const float* __restrict__ m, const float* __restrict__ v,
    const float* __restrict__ x, float* __restrict__ out)
{
    __shared__ float ws[C * C];
    __shared__ float s_inv[C], s_shift[C];
    int tid = threadIdx.x;
    for (int i = tid; i < C * C; i += 256) ws[i] = w3[i];
    if (tid < C) {
        float inv = g[tid] * rsqrtf(v[tid] + EPSBN);
        s_inv[tid] = inv;
        s_shift[tid] = bb[tid] - m[tid] * inv;
    }
    __syncthreads();

    int h = tid >> 7;
    int p = tid & 127;
    int b = blockIdx.y;
    int n = blockIdx.x * 128 + p;
    const float* up = g_U + (size_t)b * C * NSP + n;
    float uv[C];
#pragma unroll
    for (int c = 0; c < C; c++) uv[c] = up[(size_t)c * NSP];

    const float* xp = x + (size_t)b * C * NSP + n;
    float* op = out + (size_t)b * C * NSP + n;
    int o0 = h * 32;
#pragma unroll 4
    for (int o = o0; o < o0 + 32; o++) {
        const float4* wr = (const float4*)(ws + o * C);
        float a0 = 0.f, a1 = 0.f, a2 = 0.f, a3 = 0.f;
#pragma unroll
        for (int k = 0; k < 16; k++) {
            float4 f = wr[k];
            a0 += f.x * uv[4 * k + 0];
            a1 += f.y * uv[4 * k + 1];
            a2 += f.z * uv[4 * k + 2];
            a3 += f.w * uv[4 * k + 3];
        }
        float acc = (a0 + a1) + (a2 + a3);
        float r = acc * s_inv[o] + s_shift[o] + xp[(size_t)o * NSP];
        op[(size_t)o * NSP] = r;
    }
}

// ---------------------------------------------------------------------------
extern "C" void kernel_launch(void* const* d_in, const int* in_sizes, int n_in,
                              void* d_out, int out_size)
{
    const float* x    = (const float*)d_in[0];
    const float* w1   = (const float*)d_in[1];
    const float* bn1g = (const float*)d_in[2];
    const float* bn1b = (const float*)d_in[3];
    const float* bn1m = (const float*)d_in[4];
    const float* bn1v = (const float*)d_in[5];
    const float* w2   = (const float*)d_in[6];
    const float* bn2g = (const float*)d_in[7];
    const float* bn2b = (const float*)d_in[8];
    const float* bn2m = (const float*)d_in[9];
    const float* bn2v = (const float*)d_in[10];
    const float* w3   = (const float*)d_in[11];
    const float* bn3g = (const float*)d_in[12];
    const float* bn3b = (const float*)d_in[13];
    const float* bn3m = (const float*)d_in[14];
    const float* bn3v = (const float*)d_in[15];
    float* out = (float*)d_out;

    static int smem_set = 0;
    if (!smem_set) {
        cudaFuncSetAttribute(attn_mma_kernel,
                             cudaFuncAttributeMaxDynamicSharedMemorySize,
                             SMEM_U32 * 4);
        smem_set = 1;
    }

    conv1_kernel<<<dim3(NSP / 128, BB), 256>>>(x, w1, bn1g, bn1b, bn1m, bn1v);
    attn_mma_kernel<<<dim3(NSP / TNQ, BB), 256, SMEM_U32 * 4>>>(x);
    dw_kernel<<<(BB * C * NSP) / 256, 256>>>(w2, bn2g, bn2b, bn2m, bn2v);
    conv3_kernel<<<dim3(NSP / 128, BB), 256>>>(w3, bn3g, bn3b, bn3m, bn3v, x, out);
}

// round 5
// speedup vs baseline: 1.8781x; 1.5836x over previous
#include <cuda_runtime.h>
#include <cuda_bf16.h>
#include <math.h>

#define C   64
#define HW  64
#define NSP 4096          // N = HW*HW spatial positions
#define BB  8             // batch
#define EPSBN 1e-5f

// attention tiling
#define TNQ 128           // query rows per CTA
#define TMK 64            // key/value chunk
#define PQS 136           // Q smem pitch (u32, d-pair-major [32][128])
#define PKS 72            // K smem pitch (u32, d-pair-major [32][64])
#define PVS 72            // V smem pitch (u32, j-pair-major [32][64])
#define SMEM_U32 (32*PQS + 32*PKS + 32*PVS)   // 8960 u32 = 35840 B

// scale: (1/8) * log2(e)  -> logits in log2 domain, exp == exp2
#define QSCALE 0.18033688f

// scratch (no allocations allowed -> device globals)
__device__ float g_V[BB * C * NSP];     // after conv1+bn1+relu
__device__ float g_attn[BB * C * NSP];  // attention output
__device__ float g_U[BB * C * NSP];     // after depthwise+bn2+relu

// ---------------------------------------------------------------------------
// helpers
// ---------------------------------------------------------------------------
__device__ __forceinline__ unsigned packbf16(float lo, float hi) {
    unsigned r;
    asm("cvt.rn.bf16x2.f32 %0, %1, %2;" : "=r"(r) : "f"(hi), "f"(lo));
    return r;
}

__device__ __forceinline__ float ex2(float x) {
    float r;
    asm("ex2.approx.ftz.f32 %0, %1;" : "=f"(r) : "f"(x));
    return r;
}

__device__ __forceinline__ void mma_bf16(float c[4],
                                         unsigned a0, unsigned a1, unsigned a2, unsigned a3,
                                         unsigned b0, unsigned b1) {
    asm volatile(
        "mma.sync.aligned.m16n8k16.row.col.f32.bf16.bf16.f32 "
        "{%0,%1,%2,%3},{%4,%5,%6,%7},{%8,%9},{%0,%1,%2,%3};\n"
        : "+f"(c[0]), "+f"(c[1]), "+f"(c[2]), "+f"(c[3])
        : "r"(a0), "r"(a1), "r"(a2), "r"(a3), "r"(b0), "r"(b1));
}

// ---------------------------------------------------------------------------
// conv1x1 (w1) + BN1 + ReLU  ->  g_V
// ---------------------------------------------------------------------------
__global__ __launch_bounds__(256) void conv1_kernel(
    const float* __restrict__ x, const float* __restrict__ w1,
    const float* __restrict__ g, const float* __restrict__ bb,
    const float* __restrict__ m, const float* __restrict__ v)
{
    __shared__ float ws[C * C];
    __shared__ float s_inv[C], s_shift[C];
    int tid = threadIdx.x;
    for (int i = tid; i < C * C; i += 256) ws[i] = w1[i];
    if (tid < C) {
        float inv = g[tid] * rsqrtf(v[tid] + EPSBN);
        s_inv[tid] = inv;
        s_shift[tid] = bb[tid] - m[tid] * inv;
    }
    __syncthreads();

    int h = tid >> 7;                 // output half (warp-uniform)
    int p = tid & 127;
    int b = blockIdx.y;
    int n = blockIdx.x * 128 + p;
    const float* xp = x + (size_t)b * C * NSP + n;
    float xv[C];
#pragma unroll
    for (int c = 0; c < C; c++) xv[c] = xp[(size_t)c * NSP];

    float* op = g_V + (size_t)b * C * NSP + n;
    int o0 = h * 32;
#pragma unroll 4
    for (int o = o0; o < o0 + 32; o++) {
        const float4* wr = (const float4*)(ws + o * C);
        float a0 = 0.f, a1 = 0.f, a2 = 0.f, a3 = 0.f;
#pragma unroll
        for (int k = 0; k < 16; k++) {
            float4 f = wr[k];
            a0 += f.x * xv[4 * k + 0];
            a1 += f.y * xv[4 * k + 1];
            a2 += f.z * xv[4 * k + 2];
            a3 += f.w * xv[4 * k + 3];
        }
        float acc = (a0 + a1) + (a2 + a3);
        float r = acc * s_inv[o] + s_shift[o];
        op[(size_t)o * NSP] = fmaxf(r, 0.f);
    }
}

// ---------------------------------------------------------------------------
// flash attention, bf16 m16n8k16 mma, no-max softmax, C->A fragment reuse.
// CTA = (batch, 128 query rows); 8 warps; warp owns 16 rows x all 64 cols.
// ---------------------------------------------------------------------------
__global__ __launch_bounds__(256, 2) void attn_mma_kernel(const float* __restrict__ x)
{
    __shared__ unsigned Qs[32 * PQS];   // [d/2][i] bf16x2 (d, d+1)
    __shared__ unsigned Ks[32 * PKS];   // [d/2][j] bf16x2 (d, d+1)
    __shared__ unsigned Vs[32 * PVS];   // [j/2][d] bf16x2 (j, j+1)

    const int tid  = threadIdx.x;
    const int lane = tid & 31;
    const int wid  = tid >> 5;
    const int g    = lane >> 2;       // 0..7
    const int q    = lane & 3;        // 0..3
    const int i0   = wid * 16;        // warp's row base

    const int b  = blockIdx.y;
    const int n0 = blockIdx.x * TNQ;
    const float* xb = x   + (size_t)b * C * NSP;
    const float* vb = g_V + (size_t)b * C * NSP;

    // load Q tile (scale folded, packed d-pairs)
    for (int t = tid; t < 32 * 128; t += 256) {
        int dp = t >> 7, i = t & 127;
        float lo = xb[(size_t)(2 * dp) * NSP + n0 + i] * QSCALE;
        float hi = xb[(size_t)(2 * dp + 1) * NSP + n0 + i] * QSCALE;
        Qs[dp * PQS + i] = packbf16(lo, hi);
    }

    float SC[8][4];                   // S fragments (fp32)
    float OC[8][4];                   // O accumulators
    unsigned PH0[8], PH1[8];          // P packed bf16x2 (rows g / g+8)
#pragma unroll
    for (int t = 0; t < 8; t++) { OC[t][0] = OC[t][1] = OC[t][2] = OC[t][3] = 0.f; }
    float rl0 = 0.f, rl1 = 0.f;       // per-lane partial row sums

    __syncthreads();

    for (int m0 = 0; m0 < NSP; m0 += TMK) {
        // ---- load K/V chunk ----
        for (int t = tid; t < 32 * 64; t += 256) {      // K: d-pair packed
            int dp = t >> 6, j = t & 63;
            float lo = xb[(size_t)(2 * dp) * NSP + m0 + j];
            float hi = xb[(size_t)(2 * dp + 1) * NSP + m0 + j];
            Ks[dp * PKS + j] = packbf16(lo, hi);
        }
        for (int t = tid; t < 32 * 64; t += 256) {      // V: j-pair packed
            int jp = t & 31, d = t >> 5;
            float2 vv = *(const float2*)(vb + (size_t)d * NSP + m0 + 2 * jp);
            Vs[jp * PVS + d] = packbf16(vv.x, vv.y);
        }
        __syncthreads();

        // ---- S = Q K^T (log2-domain) ----
#pragma unroll
        for (int t = 0; t < 8; t++) { SC[t][0] = SC[t][1] = SC[t][2] = SC[t][3] = 0.f; }
#pragma unroll
        for (int ks = 0; ks < 4; ks++) {
            int r = ks * 8 + q;
            unsigned a0 = Qs[r * PQS + i0 + g];
            unsigned a1 = Qs[r * PQS + i0 + g + 8];
            unsigned a2 = Qs[(r + 4) * PQS + i0 + g];
            unsigned a3 = Qs[(r + 4) * PQS + i0 + g + 8];
#pragma unroll
            for (int nt = 0; nt < 8; nt++) {
                unsigned b0 = Ks[r * PKS + nt * 8 + g];
                unsigned b1 = Ks[(r + 4) * PKS + nt * 8 + g];
                mma_bf16(SC[nt], a0, a1, a2, a3, b0, b1);
            }
        }

        // ---- P = exp2(S); row sums; pack to bf16 A-fragments ----
#pragma unroll
        for (int nt = 0; nt < 8; nt++) {
            float e0 = ex2(SC[nt][0]);
            float e1 = ex2(SC[nt][1]);
            float e2 = ex2(SC[nt][2]);
            float e3 = ex2(SC[nt][3]);
            rl0 += e0 + e1;
            rl1 += e2 + e3;
            PH0[nt] = packbf16(e0, e1);   // row g,   cols 2q, 2q+1
            PH1[nt] = packbf16(e2, e3);   // row g+8, cols 2q, 2q+1
        }

        // ---- O += P V : C-layout == A-layout, zero shuffles ----
#pragma unroll
        for (int jt = 0; jt < 4; jt++) {
            unsigned a0 = PH0[2 * jt];
            unsigned a1 = PH1[2 * jt];
            unsigned a2 = PH0[2 * jt + 1];
            unsigned a3 = PH1[2 * jt + 1];
#pragma unroll
            for (int nt2 = 0; nt2 < 8; nt2++) {
                unsigned b0 = Vs[(jt * 8 + q) * PVS + nt2 * 8 + g];
                unsigned b1 = Vs[(jt * 8 + q + 4) * PVS + nt2 * 8 + g];
                mma_bf16(OC[nt2], a0, a1, a2, a3, b0, b1);
            }
        }
        __syncthreads();
    }

    // ---- final row-sum reduction ----
    rl0 += __shfl_xor_sync(0xffffffffu, rl0, 1);
    rl0 += __shfl_xor_sync(0xffffffffu, rl0, 2);
    rl1 += __shfl_xor_sync(0xffffffffu, rl1, 1);
    rl1 += __shfl_xor_sync(0xffffffffu, rl1, 2);

    // ---- normalize + write ----
    {
        float inv0 = 1.f / rl0, inv1 = 1.f / rl1;
        float* ob = g_attn + (size_t)b * C * NSP + n0 + i0 + g;
#pragma unroll
        for (int nt2 = 0; nt2 < 8; nt2++) {
            int d0 = nt2 * 8 + 2 * q;
            ob[(size_t)d0 * NSP]           = OC[nt2][0] * inv0;
            ob[(size_t)(d0 + 1) * NSP]     = OC[nt2][1] * inv0;
            ob[(size_t)d0 * NSP + 8]       = OC[nt2][2] * inv1;
            ob[(size_t)(d0 + 1) * NSP + 8] = OC[nt2][3] * inv1;
        }
    }
}

// ---------------------------------------------------------------------------
// depthwise 3x3 SAME (w2) + BN2 + ReLU : g_attn -> g_U
// ---------------------------------------------------------------------------
__global__ __launch_bounds__(256) void dw_kernel(
    const float* __restrict__ w2,
    const float* __restrict__ g, const float* __restrict__ bb,
    const float* __restrict__ m, const float* __restrict__ v)
{
    int idx = blockIdx.x * 256 + threadIdx.x;      // over BB*C*NSP
    int xw = idx & (HW - 1);
    int rest = idx >> 6;
    int y = rest & (HW - 1);
    rest >>= 6;
    int c = rest & (C - 1);
    const float* ip = g_attn + ((size_t)(idx >> 12) << 12);  // (b,c) plane base
    float acc = 0.f;
#pragma unroll
    for (int dy = -1; dy <= 1; dy++) {
        int yy = y + dy;
        if (yy < 0 || yy >= HW) continue;
#pragma unroll
        for (int dx = -1; dx <= 1; dx++) {
            int xx = xw + dx;
            if (xx < 0 || xx >= HW) continue;
            acc += ip[yy * HW + xx] * w2[c * 9 + (dy + 1) * 3 + (dx + 1)];
        }
    }
    float inv = g[c] * rsqrtf(v[c] + EPSBN);
    float r = acc * inv + (bb[c] - m[c] * inv);
    g_U[idx] = fmaxf(r, 0.f);
}

// ---------------------------------------------------------------------------
// conv1x1 (w3) + BN3 + residual(x) -> out
// ---------------------------------------------------------------------------
__global__ __launch_bounds__(256) void conv3_kernel(
    const float* __restrict__ w3,
    const float* __restrict__ g, const float* __restrict__ bb,
    const float* __restrict__ m, const float* __restrict__ v,
    const float* __restrict__ x, float* __restrict__ out)
{
    __shared__ float ws[C * C];
    __shared__ float s_inv[C], s_shift[C];
    int tid = threadIdx.x;
    for (int i = tid; i < C * C; i += 256) ws[i] = w3[i];
    if (tid < C) {
        float inv = g[tid] * rsqrtf(v[tid] + EPSBN);
        s_inv[tid] = inv;
        s_shift[tid] = bb[tid] - m[tid] * inv;
    }
    __syncthreads();

    int h = tid >> 7;
    int p = tid & 127;
    int b = blockIdx.y;
    int n = blockIdx.x * 128 + p;
    const float* up = g_U + (size_t)b * C * NSP + n;
    float uv[C];
#pragma unroll
    for (int c = 0; c < C; c++) uv[c] = up[(size_t)c * NSP];

    const float* xp = x + (size_t)b * C * NSP + n;
    float* op = out + (size_t)b * C * NSP + n;
    int o0 = h * 32;
#pragma unroll 4
    for (int o = o0; o < o0 + 32; o++) {
        const float4* wr = (const float4*)(ws + o * C);
        float a0 = 0.f, a1 = 0.f, a2 = 0.f, a3 = 0.f;
#pragma unroll
        for (int k = 0; k < 16; k++) {
            float4 f = wr[k];
            a0 += f.x * uv[4 * k + 0];
            a1 += f.y * uv[4 * k + 1];
            a2 += f.z * uv[4 * k + 2];
            a3 += f.w * uv[4 * k + 3];
        }
        float acc = (a0 + a1) + (a2 + a3);
        float r = acc * s_inv[o] + s_shift[o] + xp[(size_t)o * NSP];
        op[(size_t)o * NSP] = r;
    }
}

// ---------------------------------------------------------------------------
extern "C" void kernel_launch(void* const* d_in, const int* in_sizes, int n_in,
                              void* d_out, int out_size)
{
    const float* x    = (const float*)d_in[0];
    const float* w1   = (const float*)d_in[1];
    const float* bn1g = (const float*)d_in[2];
    const float* bn1b = (const float*)d_in[3];
    const float* bn1m = (const float*)d_in[4];
    const float* bn1v = (const float*)d_in[5];
    const float* w2   = (const float*)d_in[6];
    const float* bn2g = (const float*)d_in[7];
    const float* bn2b = (const float*)d_in[8];
    const float* bn2m = (const float*)d_in[9];
    const float* bn2v = (const float*)d_in[10];
    const float* w3   = (const float*)d_in[11];
    const float* bn3g = (const float*)d_in[12];
    const float* bn3b = (const float*)d_in[13];
    const float* bn3m = (const float*)d_in[14];
    const float* bn3v = (const float*)d_in[15];
    float* out = (float*)d_out;

    conv1_kernel<<<dim3(NSP / 128, BB), 256>>>(x, w1, bn1g, bn1b, bn1m, bn1v);
    attn_mma_kernel<<<dim3(NSP / TNQ, BB), 256>>>(x);
    dw_kernel<<<(BB * C * NSP) / 256, 256>>>(w2, bn2g, bn2b, bn2m, bn2v);
    conv3_kernel<<<dim3(NSP / 128, BB), 256>>>(w3, bn3g, bn3b, bn3m, bn3v, x, out);
}

// round 6
// speedup vs baseline: 2.0050x; 1.0676x over previous
#include <cuda_runtime.h>
#include <cuda_bf16.h>
#include <math.h>

#define C   64
#define HW  64
#define NSP 4096          // N = HW*HW spatial positions
#define BB  8             // batch
#define EPSBN 1e-5f

// attention tiling
#define TNQ 256           // query rows per CTA (8 warps x 32 rows)
#define TMK 64            // key/value chunk
#define PKS 72            // K smem pitch (u32, d-pair-major [32][64])
#define PVS 72            // V smem pitch (u32, j-pair-major [32][64])

// scale: (1/8) * log2(e)  -> logits in log2 domain, exp == exp2
#define QSCALE 0.18033688f

// scratch (no allocations allowed -> device globals)
__device__ float g_V[BB * C * NSP];     // after conv1+bn1+relu
__device__ float g_attn[BB * C * NSP];  // attention output
__device__ float g_U[BB * C * NSP];     // after depthwise+bn2+relu

// ---------------------------------------------------------------------------
// helpers
// ---------------------------------------------------------------------------
__device__ __forceinline__ unsigned packbf16(float lo, float hi) {
    unsigned r;
    asm("cvt.rn.bf16x2.f32 %0, %1, %2;" : "=r"(r) : "f"(hi), "f"(lo));
    return r;
}

__device__ __forceinline__ float ex2(float x) {
    float r;
    asm("ex2.approx.ftz.f32 %0, %1;" : "=f"(r) : "f"(x));
    return r;
}

__device__ __forceinline__ void mma_bf16(float c[4],
                                         unsigned a0, unsigned a1, unsigned a2, unsigned a3,
                                         unsigned b0, unsigned b1) {
    asm volatile(
        "mma.sync.aligned.m16n8k16.row.col.f32.bf16.bf16.f32 "
        "{%0,%1,%2,%3},{%4,%5,%6,%7},{%8,%9},{%0,%1,%2,%3};\n"
        : "+f"(c[0]), "+f"(c[1]), "+f"(c[2]), "+f"(c[3])
        : "r"(a0), "r"(a1), "r"(a2), "r"(a3), "r"(b0), "r"(b1));
}

// ---------------------------------------------------------------------------
// conv1x1 (w1) + BN1 + ReLU  ->  g_V
// ---------------------------------------------------------------------------
__global__ __launch_bounds__(256) void conv1_kernel(
    const float* __restrict__ x, const float* __restrict__ w1,
    const float* __restrict__ g, const float* __restrict__ bb,
    const float* __restrict__ m, const float* __restrict__ v)
{
    __shared__ float ws[C * C];
    __shared__ float s_inv[C], s_shift[C];
    int tid = threadIdx.x;
    for (int i = tid; i < C * C; i += 256) ws[i] = w1[i];
    if (tid < C) {
        float inv = g[tid] * rsqrtf(v[tid] + EPSBN);
        s_inv[tid] = inv;
        s_shift[tid] = bb[tid] - m[tid] * inv;
    }
    __syncthreads();

    int h = tid >> 7;                 // output half (warp-uniform)
    int p = tid & 127;
    int b = blockIdx.y;
    int n = blockIdx.x * 128 + p;
    const float* xp = x + (size_t)b * C * NSP + n;
    float xv[C];
#pragma unroll
    for (int c = 0; c < C; c++) xv[c] = xp[(size_t)c * NSP];

    float* op = g_V + (size_t)b * C * NSP + n;
    int o0 = h * 32;
#pragma unroll 4
    for (int o = o0; o < o0 + 32; o++) {
        const float4* wr = (const float4*)(ws + o * C);
        float a0 = 0.f, a1 = 0.f, a2 = 0.f, a3 = 0.f;
#pragma unroll
        for (int k = 0; k < 16; k++) {
            float4 f = wr[k];
            a0 += f.x * xv[4 * k + 0];
            a1 += f.y * xv[4 * k + 1];
            a2 += f.z * xv[4 * k + 2];
            a3 += f.w * xv[4 * k + 3];
        }
        float acc = (a0 + a1) + (a2 + a3);
        float r = acc * s_inv[o] + s_shift[o];
        op[(size_t)o * NSP] = fmaxf(r, 0.f);
    }
}

// ---------------------------------------------------------------------------
// flash attention, bf16 m16n8k16 mma, no-max softmax, Q in registers.
// CTA = (batch, 256 query rows); 8 warps; warp owns 32 rows (2 row-blocks)
// sharing K/V B-fragments. Grid = 128 CTAs = one wave.
// ---------------------------------------------------------------------------
__global__ __launch_bounds__(256) void attn_mma_kernel(const float* __restrict__ x)
{
    __shared__ unsigned Ks[32 * PKS];   // [d/2][j] bf16x2 (d, d+1)
    __shared__ unsigned Vs[32 * PVS];   // [j/2][d] bf16x2 (j, j+1)

    const int tid  = threadIdx.x;
    const int lane = tid & 31;
    const int wid  = tid >> 5;
    const int g    = lane >> 2;       // 0..7
    const int q    = lane & 3;        // 0..3
    const int i0   = wid * 32;        // warp's row base

    const int b  = blockIdx.y;
    const int n0 = blockIdx.x * TNQ;
    const float* xb = x   + (size_t)b * C * NSP;
    const float* vb = g_V + (size_t)b * C * NSP;

    // ---- Q A-fragments straight into registers (scale folded) ----
    unsigned QA[4][2][4];
#pragma unroll
    for (int ks = 0; ks < 4; ks++) {
#pragma unroll
        for (int rb = 0; rb < 2; rb++) {
            int re = n0 + i0 + rb * 16 + g;      // even row (A rows g / g+8)
            int d0 = 16 * ks + 2 * q;
            QA[ks][rb][0] = packbf16(xb[(size_t)d0 * NSP + re] * QSCALE,
                                     xb[(size_t)(d0 + 1) * NSP + re] * QSCALE);
            QA[ks][rb][1] = packbf16(xb[(size_t)d0 * NSP + re + 8] * QSCALE,
                                     xb[(size_t)(d0 + 1) * NSP + re + 8] * QSCALE);
            QA[ks][rb][2] = packbf16(xb[(size_t)(d0 + 8) * NSP + re] * QSCALE,
                                     xb[(size_t)(d0 + 9) * NSP + re] * QSCALE);
            QA[ks][rb][3] = packbf16(xb[(size_t)(d0 + 8) * NSP + re + 8] * QSCALE,
                                     xb[(size_t)(d0 + 9) * NSP + re + 8] * QSCALE);
        }
    }

    float SC[2][8][4];                // S fragments per row-block
    float OC[2][8][4];                // O accumulators
    unsigned PH[2][8][2];             // P bf16x2 A-fragments per row-block
#pragma unroll
    for (int rb = 0; rb < 2; rb++)
#pragma unroll
        for (int t = 0; t < 8; t++)
            OC[rb][t][0] = OC[rb][t][1] = OC[rb][t][2] = OC[rb][t][3] = 0.f;
    float rl[2][2] = {{0.f, 0.f}, {0.f, 0.f}};

    for (int m0 = 0; m0 < NSP; m0 += TMK) {
        __syncthreads();              // prev chunk compute done reading K/V
        // ---- load K/V chunk ----
        for (int t = tid; t < 32 * 64; t += 256) {      // K: d-pair packed
            int dp = t >> 6, j = t & 63;
            float lo = xb[(size_t)(2 * dp) * NSP + m0 + j];
            float hi = xb[(size_t)(2 * dp + 1) * NSP + m0 + j];
            Ks[dp * PKS + j] = packbf16(lo, hi);
        }
        for (int t = tid; t < 32 * 64; t += 256) {      // V: j-pair packed
            int jp = t & 31, d = t >> 5;
            float2 vv = *(const float2*)(vb + (size_t)d * NSP + m0 + 2 * jp);
            Vs[jp * PVS + d] = packbf16(vv.x, vv.y);
        }
        __syncthreads();

        // ---- S = Q K^T (K fragments shared across both row-blocks) ----
#pragma unroll
        for (int rb = 0; rb < 2; rb++)
#pragma unroll
            for (int t = 0; t < 8; t++)
                SC[rb][t][0] = SC[rb][t][1] = SC[rb][t][2] = SC[rb][t][3] = 0.f;
#pragma unroll
        for (int ks = 0; ks < 4; ks++) {
            int r = ks * 8 + q;
#pragma unroll
            for (int nt = 0; nt < 8; nt++) {
                unsigned b0 = Ks[r * PKS + nt * 8 + g];
                unsigned b1 = Ks[(r + 4) * PKS + nt * 8 + g];
                mma_bf16(SC[0][nt], QA[ks][0][0], QA[ks][0][1], QA[ks][0][2], QA[ks][0][3], b0, b1);
                mma_bf16(SC[1][nt], QA[ks][1][0], QA[ks][1][1], QA[ks][1][2], QA[ks][1][3], b0, b1);
            }
        }

        // ---- P = exp2(S); per-lane row sums; pack to A-fragments ----
#pragma unroll
        for (int rb = 0; rb < 2; rb++) {
#pragma unroll
            for (int nt = 0; nt < 8; nt++) {
                float e0 = ex2(SC[rb][nt][0]);
                float e1 = ex2(SC[rb][nt][1]);
                float e2 = ex2(SC[rb][nt][2]);
                float e3 = ex2(SC[rb][nt][3]);
                rl[rb][0] += e0 + e1;
                rl[rb][1] += e2 + e3;
                PH[rb][nt][0] = packbf16(e0, e1);   // row g,   cols 2q,2q+1
                PH[rb][nt][1] = packbf16(e2, e3);   // row g+8, cols 2q,2q+1
            }
        }

        // ---- O += P V (V fragments shared across both row-blocks) ----
#pragma unroll
        for (int jt = 0; jt < 4; jt++) {
            unsigned aA0 = PH[0][2 * jt][0],     aA1 = PH[0][2 * jt][1];
            unsigned aA2 = PH[0][2 * jt + 1][0], aA3 = PH[0][2 * jt + 1][1];
            unsigned aB0 = PH[1][2 * jt][0],     aB1 = PH[1][2 * jt][1];
            unsigned aB2 = PH[1][2 * jt + 1][0], aB3 = PH[1][2 * jt + 1][1];
#pragma unroll
            for (int nt2 = 0; nt2 < 8; nt2++) {
                unsigned b0 = Vs[(jt * 8 + q) * PVS + nt2 * 8 + g];
                unsigned b1 = Vs[(jt * 8 + q + 4) * PVS + nt2 * 8 + g];
                mma_bf16(OC[0][nt2], aA0, aA1, aA2, aA3, b0, b1);
                mma_bf16(OC[1][nt2], aB0, aB1, aB2, aB3, b0, b1);
            }
        }
    }

    // ---- final row-sum reduction (across the 4 q-lanes per row) ----
#pragma unroll
    for (int rb = 0; rb < 2; rb++) {
        rl[rb][0] += __shfl_xor_sync(0xffffffffu, rl[rb][0], 1);
        rl[rb][0] += __shfl_xor_sync(0xffffffffu, rl[rb][0], 2);
        rl[rb][1] += __shfl_xor_sync(0xffffffffu, rl[rb][1], 1);
        rl[rb][1] += __shfl_xor_sync(0xffffffffu, rl[rb][1], 2);
    }

    // ---- normalize + write ----
#pragma unroll
    for (int rb = 0; rb < 2; rb++) {
        float inv0 = 1.f / rl[rb][0], inv1 = 1.f / rl[rb][1];
        float* ob = g_attn + (size_t)b * C * NSP + n0 + i0 + rb * 16 + g;
#pragma unroll
        for (int nt2 = 0; nt2 < 8; nt2++) {
            int d0 = nt2 * 8 + 2 * q;
            ob[(size_t)d0 * NSP]           = OC[rb][nt2][0] * inv0;
            ob[(size_t)(d0 + 1) * NSP]     = OC[rb][nt2][1] * inv0;
            ob[(size_t)d0 * NSP + 8]       = OC[rb][nt2][2] * inv1;
            ob[(size_t)(d0 + 1) * NSP + 8] = OC[rb][nt2][3] * inv1;
        }
    }
}

// ---------------------------------------------------------------------------
// depthwise 3x3 SAME (w2) + BN2 + ReLU : g_attn -> g_U
// ---------------------------------------------------------------------------
__global__ __launch_bounds__(256) void dw_kernel(
    const float* __restrict__ w2,
    const float* __restrict__ g, const float* __restrict__ bb,
    const float* __restrict__ m, const float* __restrict__ v)
{
    int idx = blockIdx.x * 256 + threadIdx.x;      // over BB*C*NSP
    int xw = idx & (HW - 1);
    int rest = idx >> 6;
    int y = rest & (HW - 1);
    rest >>= 6;
    int c = rest & (C - 1);
    const float* ip = g_attn + ((size_t)(idx >> 12) << 12);  // (b,c) plane base
    float acc = 0.f;
#pragma unroll
    for (int dy = -1; dy <= 1; dy++) {
        int yy = y + dy;
        if (yy < 0 || yy >= HW) continue;
#pragma unroll
        for (int dx = -1; dx <= 1; dx++) {
            int xx = xw + dx;
            if (xx < 0 || xx >= HW) continue;
            acc += ip[yy * HW + xx] * w2[c * 9 + (dy + 1) * 3 + (dx + 1)];
        }
    }
    float inv = g[c] * rsqrtf(v[c] + EPSBN);
    float r = acc * inv + (bb[c] - m[c] * inv);
    g_U[idx] = fmaxf(r, 0.f);
}

// ---------------------------------------------------------------------------
// conv1x1 (w3) + BN3 + residual(x) -> out
// ---------------------------------------------------------------------------
__global__ __launch_bounds__(256) void conv3_kernel(
    const float* __restrict__ w3,
    const float* __restrict__ g, const float* __restrict__ bb,
    const float* __restrict__ m, const float* __restrict__ v,
    const float* __restrict__ x, float* __restrict__ out)
{
    __shared__ float ws[C * C];
    __shared__ float s_inv[C], s_shift[C];
    int tid = threadIdx.x;
    for (int i = tid; i < C * C; i += 256) ws[i] = w3[i];
    if (tid < C) {
        float inv = g[tid] * rsqrtf(v[tid] + EPSBN);
        s_inv[tid] = inv;
        s_shift[tid] = bb[tid] - m[tid] * inv;
    }
    __syncthreads();

    int h = tid >> 7;
    int p = tid & 127;
    int b = blockIdx.y;
    int n = blockIdx.x * 128 + p;
    const float* up = g_U + (size_t)b * C * NSP + n;
    float uv[C];
#pragma unroll
    for (int c = 0; c < C; c++) uv[c] = up[(size_t)c * NSP];

    const float* xp = x + (size_t)b * C * NSP + n;
    float* op = out + (size_t)b * C * NSP + n;
    int o0 = h * 32;
#pragma unroll 4
    for (int o = o0; o < o0 + 32; o++) {
        const float4* wr = (const float4*)(ws + o * C);
        float a0 = 0.f, a1 = 0.f, a2 = 0.f, a3 = 0.f;
#pragma unroll
        for (int k = 0; k < 16; k++) {
            float4 f = wr[k];
            a0 += f.x * uv[4 * k + 0];
            a1 += f.y * uv[4 * k + 1];
            a2 += f.z * uv[4 * k + 2];
            a3 += f.w * uv[4 * k + 3];
        }
        float acc = (a0 + a1) + (a2 + a3);
        float r = acc * s_inv[o] + s_shift[o] + xp[(size_t)o * NSP];
        op[(size_t)o * NSP] = r;
    }
}

// ---------------------------------------------------------------------------
extern "C" void kernel_launch(void* const* d_in, const int* in_sizes, int n_in,
                              void* d_out, int out_size)
{
    const float* x    = (const float*)d_in[0];
    const float* w1   = (const float*)d_in[1];
    const float* bn1g = (const float*)d_in[2];
    const float* bn1b = (const float*)d_in[3];
    const float* bn1m = (const float*)d_in[4];
    const float* bn1v = (const float*)d_in[5];
    const float* w2   = (const float*)d_in[6];
    const float* bn2g = (const float*)d_in[7];
    const float* bn2b = (const float*)d_in[8];
    const float* bn2m = (const float*)d_in[9];
    const float* bn2v = (const float*)d_in[10];
    const float* w3   = (const float*)d_in[11];
    const float* bn3g = (const float*)d_in[12];
    const float* bn3b = (const float*)d_in[13];
    const float* bn3m = (const float*)d_in[14];
    const float* bn3v = (const float*)d_in[15];
    float* out = (float*)d_out;

    conv1_kernel<<<dim3(NSP / 128, BB), 256>>>(x, w1, bn1g, bn1b, bn1m, bn1v);
    attn_mma_kernel<<<dim3(NSP / TNQ, BB), 256>>>(x);
    dw_kernel<<<(BB * C * NSP) / 256, 256>>>(w2, bn2g, bn2b, bn2m, bn2v);
    conv3_kernel<<<dim3(NSP / 128, BB), 256>>>(w3, bn3g, bn3b, bn3m, bn3v, x, out);
}

// round 7
// speedup vs baseline: 3.0214x; 1.5069x over previous
#include <cuda_runtime.h>
#include <cuda_bf16.h>
#include <math.h>

#define C   64
#define HW  64
#define NSP 4096          // N = HW*HW spatial positions
#define BB  8             // batch
#define EPSBN 1e-5f

// attention tiling
#define TNQ 256           // query rows per CTA (8 warps x 32 rows)
#define TMK 64            // key/value chunk
#define PKS 72            // K smem pitch (u32): [d/2=32][64]
#define PVN 36            // V smem pitch (u32): [d=64][j/2=32]

// scale: (1/8) * log2(e)  -> logits in log2 domain, exp == exp2
#define QSCALE 0.18033688f

// scratch (no allocations allowed -> device globals)
__device__ unsigned g_Kbf[BB * 32 * NSP];    // K packed bf16x2 over d-pairs, [b][dp][n]
__device__ unsigned g_Vbf[BB * 64 * 2048];   // V packed bf16x2 over n-pairs, [b][d][np]
__device__ float g_attn[BB * C * NSP];       // attention output
__device__ float g_U[BB * C * NSP];          // after depthwise+bn2+relu

// ---------------------------------------------------------------------------
// helpers
// ---------------------------------------------------------------------------
__device__ __forceinline__ unsigned packbf16(float lo, float hi) {
    unsigned r;
    asm("cvt.rn.bf16x2.f32 %0, %1, %2;" : "=r"(r) : "f"(hi), "f"(lo));
    return r;
}

__device__ __forceinline__ float ex2(float x) {
    float r;
    asm("ex2.approx.ftz.f32 %0, %1;" : "=f"(r) : "f"(x));
    return r;
}

__device__ __forceinline__ void mma_bf16(float c[4],
                                         unsigned a0, unsigned a1, unsigned a2, unsigned a3,
                                         unsigned b0, unsigned b1) {
    asm volatile(
        "mma.sync.aligned.m16n8k16.row.col.f32.bf16.bf16.f32 "
        "{%0,%1,%2,%3},{%4,%5,%6,%7},{%8,%9},{%0,%1,%2,%3};\n"
        : "+f"(c[0]), "+f"(c[1]), "+f"(c[2]), "+f"(c[3])
        : "r"(a0), "r"(a1), "r"(a2), "r"(a3), "r"(b0), "r"(b1));
}

__device__ __forceinline__ void cpa16(unsigned smem_addr, const void* gptr) {
    asm volatile("cp.async.cg.shared.global [%0], [%1], 16;"
                 :: "r"(smem_addr), "l"(gptr));
}

// ---------------------------------------------------------------------------
// conv1x1 (w1) + BN1 + ReLU -> g_Vbf (packed bf16x2 n-pairs)
// also packs K = x into g_Kbf (bf16x2 d-pairs)
// ---------------------------------------------------------------------------
__global__ __launch_bounds__(256) void conv1_kernel(
    const float* __restrict__ x, const float* __restrict__ w1,
    const float* __restrict__ g, const float* __restrict__ bb,
    const float* __restrict__ m, const float* __restrict__ v)
{
    __shared__ float ws[C * C];
    __shared__ float s_inv[C], s_shift[C];
    int tid = threadIdx.x;
    for (int i = tid; i < C * C; i += 256) ws[i] = w1[i];
    if (tid < C) {
        float inv = g[tid] * rsqrtf(v[tid] + EPSBN);
        s_inv[tid] = inv;
        s_shift[tid] = bb[tid] - m[tid] * inv;
    }
    __syncthreads();

    int h = tid >> 7;                 // output half (warp-uniform)
    int p = tid & 127;
    int b = blockIdx.y;
    int n = blockIdx.x * 128 + p;
    const float* xp = x + (size_t)b * C * NSP + n;
    float xv[C];
#pragma unroll
    for (int c = 0; c < C; c++) xv[c] = xp[(size_t)c * NSP];

    // ---- K packing (h==0 threads only; d-pairs within thread) ----
    if (h == 0) {
        unsigned* kp = g_Kbf + (size_t)b * 32 * NSP + n;
#pragma unroll
        for (int dp = 0; dp < 32; dp++)
            kp[(size_t)dp * NSP] = packbf16(xv[2 * dp], xv[2 * dp + 1]);
    }

    // ---- conv + BN + ReLU into registers ----
    float vout[32];
    int o0 = h * 32;
#pragma unroll 4
    for (int oo = 0; oo < 32; oo++) {
        int o = o0 + oo;
        const float4* wr = (const float4*)(ws + o * C);
        float a0 = 0.f, a1 = 0.f, a2 = 0.f, a3 = 0.f;
#pragma unroll
        for (int k = 0; k < 16; k++) {
            float4 f = wr[k];
            a0 += f.x * xv[4 * k + 0];
            a1 += f.y * xv[4 * k + 1];
            a2 += f.z * xv[4 * k + 2];
            a3 += f.w * xv[4 * k + 3];
        }
        float acc = (a0 + a1) + (a2 + a3);
        vout[oo] = fmaxf(acc * s_inv[o] + s_shift[o], 0.f);
    }

    // ---- V packing: n-pairs via lane shuffle (even lanes write) ----
    bool evenl = !(n & 1);
    unsigned* vp = g_Vbf + (size_t)b * 64 * 2048 + (n >> 1);
#pragma unroll
    for (int oo = 0; oo < 32; oo++) {
        float other = __shfl_down_sync(0xffffffffu, vout[oo], 1);
        if (evenl)
            vp[(size_t)(o0 + oo) * 2048] = packbf16(vout[oo], other);
    }
}

// ---------------------------------------------------------------------------
// flash attention, bf16 m16n8k16, no-max softmax, Q in regs,
// K/V double-buffered via cp.async from pre-packed bf16 arrays.
// CTA = (batch, 256 rows); 8 warps x 32 rows; grid 128 CTAs = 1 wave.
// ---------------------------------------------------------------------------
__global__ __launch_bounds__(256) void attn_mma_kernel(const float* __restrict__ x)
{
    __shared__ unsigned Ks[2][32 * PKS];
    __shared__ unsigned Vs[2][64 * PVN];

    const int tid  = threadIdx.x;
    const int lane = tid & 31;
    const int wid  = tid >> 5;
    const int g    = lane >> 2;       // 0..7
    const int q    = lane & 3;        // 0..3
    const int i0   = wid * 32;

    const int b  = blockIdx.y;
    const int n0 = blockIdx.x * TNQ;
    const float* xb = x + (size_t)b * C * NSP;
    const unsigned* kb = g_Kbf + (size_t)b * 32 * NSP;
    const unsigned* vbp = g_Vbf + (size_t)b * 64 * 2048;

    // per-thread cp.async source/dest precompute
    const int kt4a = tid * 4;                 // K copy 0: dp, j
    const int kt4b = (tid + 256) * 4;         // K copy 1
    const int vdA = (tid * 4) >> 5, vjA = (tid * 4) & 31;
    const int vdB = ((tid + 256) * 4) >> 5, vjB = ((tid + 256) * 4) & 31;
    unsigned ksa[2], vsa[2];
    ksa[0] = (unsigned)__cvta_generic_to_shared(&Ks[0][0]);
    ksa[1] = (unsigned)__cvta_generic_to_shared(&Ks[1][0]);
    vsa[0] = (unsigned)__cvta_generic_to_shared(&Vs[0][0]);
    vsa[1] = (unsigned)__cvta_generic_to_shared(&Vs[1][0]);

    // ---- Q A-fragments straight into registers (scale folded) ----
    unsigned QA[4][2][4];
#pragma unroll
    for (int ks = 0; ks < 4; ks++) {
#pragma unroll
        for (int rb = 0; rb < 2; rb++) {
            int re = n0 + i0 + rb * 16 + g;
            int d0 = 16 * ks + 2 * q;
            QA[ks][rb][0] = packbf16(xb[(size_t)d0 * NSP + re] * QSCALE,
                                     xb[(size_t)(d0 + 1) * NSP + re] * QSCALE);
            QA[ks][rb][1] = packbf16(xb[(size_t)d0 * NSP + re + 8] * QSCALE,
                                     xb[(size_t)(d0 + 1) * NSP + re + 8] * QSCALE);
            QA[ks][rb][2] = packbf16(xb[(size_t)(d0 + 8) * NSP + re] * QSCALE,
                                     xb[(size_t)(d0 + 9) * NSP + re] * QSCALE);
            QA[ks][rb][3] = packbf16(xb[(size_t)(d0 + 8) * NSP + re + 8] * QSCALE,
                                     xb[(size_t)(d0 + 9) * NSP + re + 8] * QSCALE);
        }
    }

    float SC[2][8][4];
    float OC[2][8][4];
    unsigned PH[2][8][2];
#pragma unroll
    for (int rb = 0; rb < 2; rb++)
#pragma unroll
        for (int t = 0; t < 8; t++)
            OC[rb][t][0] = OC[rb][t][1] = OC[rb][t][2] = OC[rb][t][3] = 0.f;
    float rl[2][2] = {{0.f, 0.f}, {0.f, 0.f}};

    // issue K/V chunk m0 into buffer buf (each thread: 2 K + 2 V copies)
    #define ISSUE_CHUNK(m0, buf) do {                                             \
        int _dpA = kt4a >> 6, _jA = kt4a & 63;                                    \
        int _dpB = kt4b >> 6, _jB = kt4b & 63;                                    \
        cpa16(ksa[buf] + (_dpA * PKS + _jA) * 4, kb + (size_t)_dpA * NSP + (m0) + _jA); \
        cpa16(ksa[buf] + (_dpB * PKS + _jB) * 4, kb + (size_t)_dpB * NSP + (m0) + _jB); \
        cpa16(vsa[buf] + (vdA * PVN + vjA) * 4, vbp + (size_t)vdA * 2048 + ((m0) >> 1) + vjA); \
        cpa16(vsa[buf] + (vdB * PVN + vjB) * 4, vbp + (size_t)vdB * 2048 + ((m0) >> 1) + vjB); \
        asm volatile("cp.async.commit_group;");                                   \
    } while (0)

    ISSUE_CHUNK(0, 0);

    for (int m = 0; m < NSP / TMK; m++) {
        int cur = m & 1;
        if (m + 1 < NSP / TMK) {
            ISSUE_CHUNK((m + 1) * TMK, 1 - cur);
            asm volatile("cp.async.wait_group 1;");
        } else {
            asm volatile("cp.async.wait_group 0;");
        }
        __syncthreads();

        const unsigned* Kc = Ks[cur];
        const unsigned* Vc = Vs[cur];

        // ---- S = Q K^T ----
#pragma unroll
        for (int rb = 0; rb < 2; rb++)
#pragma unroll
            for (int t = 0; t < 8; t++)
                SC[rb][t][0] = SC[rb][t][1] = SC[rb][t][2] = SC[rb][t][3] = 0.f;
#pragma unroll
        for (int ks = 0; ks < 4; ks++) {
            int r = ks * 8 + q;
#pragma unroll
            for (int nt = 0; nt < 8; nt++) {
                unsigned b0 = Kc[r * PKS + nt * 8 + g];
                unsigned b1 = Kc[(r + 4) * PKS + nt * 8 + g];
                mma_bf16(SC[0][nt], QA[ks][0][0], QA[ks][0][1], QA[ks][0][2], QA[ks][0][3], b0, b1);
                mma_bf16(SC[1][nt], QA[ks][1][0], QA[ks][1][1], QA[ks][1][2], QA[ks][1][3], b0, b1);
            }
        }

        // ---- P = exp2(S); row sums; pack to A-fragments ----
#pragma unroll
        for (int rb = 0; rb < 2; rb++) {
#pragma unroll
            for (int nt = 0; nt < 8; nt++) {
                float e0 = ex2(SC[rb][nt][0]);
                float e1 = ex2(SC[rb][nt][1]);
                float e2 = ex2(SC[rb][nt][2]);
                float e3 = ex2(SC[rb][nt][3]);
                rl[rb][0] += e0 + e1;
                rl[rb][1] += e2 + e3;
                PH[rb][nt][0] = packbf16(e0, e1);
                PH[rb][nt][1] = packbf16(e2, e3);
            }
        }

        // ---- O += P V ----
#pragma unroll
        for (int jt = 0; jt < 4; jt++) {
            unsigned aA0 = PH[0][2 * jt][0],     aA1 = PH[0][2 * jt][1];
            unsigned aA2 = PH[0][2 * jt + 1][0], aA3 = PH[0][2 * jt + 1][1];
            unsigned aB0 = PH[1][2 * jt][0],     aB1 = PH[1][2 * jt][1];
            unsigned aB2 = PH[1][2 * jt + 1][0], aB3 = PH[1][2 * jt + 1][1];
#pragma unroll
            for (int nt2 = 0; nt2 < 8; nt2++) {
                unsigned b0 = Vc[(nt2 * 8 + g) * PVN + jt * 8 + q];
                unsigned b1 = Vc[(nt2 * 8 + g) * PVN + jt * 8 + q + 4];
                mma_bf16(OC[0][nt2], aA0, aA1, aA2, aA3, b0, b1);
                mma_bf16(OC[1][nt2], aB0, aB1, aB2, aB3, b0, b1);
            }
        }
        __syncthreads();
    }

    // ---- final row-sum reduction ----
#pragma unroll
    for (int rb = 0; rb < 2; rb++) {
        rl[rb][0] += __shfl_xor_sync(0xffffffffu, rl[rb][0], 1);
        rl[rb][0] += __shfl_xor_sync(0xffffffffu, rl[rb][0], 2);
        rl[rb][1] += __shfl_xor_sync(0xffffffffu, rl[rb][1], 1);
        rl[rb][1] += __shfl_xor_sync(0xffffffffu, rl[rb][1], 2);
    }

    // ---- normalize + write ----
#pragma unroll
    for (int rb = 0; rb < 2; rb++) {
        float inv0 = 1.f / rl[rb][0], inv1 = 1.f / rl[rb][1];
        float* ob = g_attn + (size_t)b * C * NSP + n0 + i0 + rb * 16 + g;
#pragma unroll
        for (int nt2 = 0; nt2 < 8; nt2++) {
            int d0 = nt2 * 8 + 2 * q;
            ob[(size_t)d0 * NSP]           = OC[rb][nt2][0] * inv0;
            ob[(size_t)(d0 + 1) * NSP]     = OC[rb][nt2][1] * inv0;
            ob[(size_t)d0 * NSP + 8]       = OC[rb][nt2][2] * inv1;
            ob[(size_t)(d0 + 1) * NSP + 8] = OC[rb][nt2][3] * inv1;
        }
    }
    #undef ISSUE_CHUNK
}

// ---------------------------------------------------------------------------
// depthwise 3x3 SAME (w2) + BN2 + ReLU : g_attn -> g_U ; 4 outputs/thread
// ---------------------------------------------------------------------------
__global__ __launch_bounds__(256) void dw_kernel(
    const float* __restrict__ w2,
    const float* __restrict__ g, const float* __restrict__ bb,
    const float* __restrict__ m, const float* __restrict__ v)
{
    int t = blockIdx.x * 256 + threadIdx.x;        // over BB*C*NSP/4
    int idx = t * 4;
    int xw = idx & (HW - 1);                       // multiple of 4
    int y = (idx >> 6) & (HW - 1);
    int plane = idx >> 12;                         // b*C + c
    int c = plane & (C - 1);
    const float* ip = g_attn + ((size_t)plane << 12);

    float w[9];
#pragma unroll
    for (int k = 0; k < 9; k++) w[k] = w2[c * 9 + k];

    float acc0 = 0.f, acc1 = 0.f, acc2 = 0.f, acc3 = 0.f;
#pragma unroll
    for (int dy = -1; dy <= 1; dy++) {
        int yy = y + dy;
        if (yy < 0 || yy >= HW) continue;
        const float* rp = ip + yy * HW + xw;
        float4 mid = *(const float4*)rp;
        float lft = (xw > 0) ? rp[-1] : 0.f;
        float rgt = (xw + 4 < HW) ? rp[4] : 0.f;
        float c0 = w[(dy + 1) * 3 + 0];
        float c1 = w[(dy + 1) * 3 + 1];
        float c2 = w[(dy + 1) * 3 + 2];
        acc0 += c0 * lft   + c1 * mid.x + c2 * mid.y;
        acc1 += c0 * mid.x + c1 * mid.y + c2 * mid.z;
        acc2 += c0 * mid.y + c1 * mid.z + c2 * mid.w;
        acc3 += c0 * mid.z + c1 * mid.w + c2 * rgt;
    }
    float inv = g[c] * rsqrtf(v[c] + EPSBN);
    float sh = bb[c] - m[c] * inv;
    float4 r;
    r.x = fmaxf(acc0 * inv + sh, 0.f);
    r.y = fmaxf(acc1 * inv + sh, 0.f);
    r.z = fmaxf(acc2 * inv + sh, 0.f);
    r.w = fmaxf(acc3 * inv + sh, 0.f);
    *(float4*)(g_U + idx) = r;
}

// ---------------------------------------------------------------------------
// conv1x1 (w3) + BN3 + residual(x) -> out ; 4-way output split for occupancy
// ---------------------------------------------------------------------------
__global__ __launch_bounds__(256) void conv3_kernel(
    const float* __restrict__ w3,
    const float* __restrict__ g, const float* __restrict__ bb,
    const float* __restrict__ m, const float* __restrict__ v,
    const float* __restrict__ x, float* __restrict__ out)
{
    __shared__ float ws[C * C];
    __shared__ float s_inv[C], s_shift[C];
    int tid = threadIdx.x;
    for (int i = tid; i < C * C; i += 256) ws[i] = w3[i];
    if (tid < C) {
        float inv = g[tid] * rsqrtf(v[tid] + EPSBN);
        s_inv[tid] = inv;
        s_shift[tid] = bb[tid] - m[tid] * inv;
    }
    __syncthreads();

    int h = tid >> 6;                 // quarter 0..3 (warp-uniform per 2 warps)
    int p = tid & 63;
    int b = blockIdx.y;
    int n = blockIdx.x * 64 + p;
    const float* up = g_U + (size_t)b * C * NSP + n;
    float uv[C];
#pragma unroll
    for (int c = 0; c < C; c++) uv[c] = up[(size_t)c * NSP];

    const float* xp = x + (size_t)b * C * NSP + n;
    float* op = out + (size_t)b * C * NSP + n;
    int o0 = h * 16;
#pragma unroll 4
    for (int o = o0; o < o0 + 16; o++) {
        const float4* wr = (const float4*)(ws + o * C);
        float a0 = 0.f, a1 = 0.f, a2 = 0.f, a3 = 0.f;
#pragma unroll
        for (int k = 0; k < 16; k++) {
            float4 f = wr[k];
            a0 += f.x * uv[4 * k + 0];
            a1 += f.y * uv[4 * k + 1];
            a2 += f.z * uv[4 * k + 2];
            a3 += f.w * uv[4 * k + 3];
        }
        float acc = (a0 + a1) + (a2 + a3);
        float r = acc * s_inv[o] + s_shift[o] + xp[(size_t)o * NSP];
        op[(size_t)o * NSP] = r;
    }
}

// ---------------------------------------------------------------------------
extern "C" void kernel_launch(void* const* d_in, const int* in_sizes, int n_in,
                              void* d_out, int out_size)
{
    const float* x    = (const float*)d_in[0];
    const float* w1   = (const float*)d_in[1];
    const float* bn1g = (const float*)d_in[2];
    const float* bn1b = (const float*)d_in[3];
    const float* bn1m = (const float*)d_in[4];
    const float* bn1v = (const float*)d_in[5];
    const float* w2   = (const float*)d_in[6];
    const float* bn2g = (const float*)d_in[7];
    const float* bn2b = (const float*)d_in[8];
    const float* bn2m = (const float*)d_in[9];
    const float* bn2v = (const float*)d_in[10];
    const float* w3   = (const float*)d_in[11];
    const float* bn3g = (const float*)d_in[12];
    const float* bn3b = (const float*)d_in[13];
    const float* bn3m = (const float*)d_in[14];
    const float* bn3v = (const float*)d_in[15];
    float* out = (float*)d_out;

    conv1_kernel<<<dim3(NSP / 128, BB), 256>>>(x, w1, bn1g, bn1b, bn1m, bn1v);
    attn_mma_kernel<<<dim3(NSP / TNQ, BB), 256>>>(x);
    dw_kernel<<<(BB * C * NSP / 4) / 256, 256>>>(w2, bn2g, bn2b, bn2m, bn2v);
    conv3_kernel<<<dim3(NSP / 64, BB), 256>>>(w3, bn3g, bn3b, bn3m, bn3v, x, out);
}